// round 1
// baseline (speedup 1.0000x reference)
#include <cuda_runtime.h>
#include <cstdint>

#define NN   100000
#define EE   1600000
#define IND  512
#define HIDD 256
#define OD   48
#define KIT  10

// ---------------- scratch (no allocations allowed) ----------------
__device__ float g_h1[(size_t)NN * HIDD];   // MLP hidden       (~102 MB)
__device__ float g_h0[(size_t)NN * OD];     // MLP output (teleport anchor)
__device__ float g_hs[(size_t)NN * OD];     // h * norm_out (gather source)
__device__ float g_agg[(size_t)NN * OD];    // scatter accumulator
__device__ float g_no[NN];                  // deg_out^-1/2
__device__ float g_ni[NN];                  // deg_in^-1/2
__device__ int   g_deg[2 * NN];

// ---------------- degrees ----------------
__global__ void zero_deg_kernel() {
    int i = blockIdx.x * blockDim.x + threadIdx.x;
    if (i < 2 * NN) g_deg[i] = 0;
}

__global__ void count_deg_kernel(const int* __restrict__ src, const int* __restrict__ dst) {
    int e = blockIdx.x * blockDim.x + threadIdx.x;
    if (e < EE) {
        atomicAdd(&g_deg[src[e]], 1);
        atomicAdd(&g_deg[NN + dst[e]], 1);
    }
}

__global__ void norm_kernel() {
    int i = blockIdx.x * blockDim.x + threadIdx.x;
    if (i < NN) {
        g_no[i] = rsqrtf(fmaxf((float)g_deg[i], 1.0f));
        g_ni[i] = rsqrtf(fmaxf((float)g_deg[NN + i], 1.0f));
    }
}

// ---------------- GEMM1: h1 = relu(feats @ W1 + b1) ----------------
// 128x64 block tile, BK=16, 256 threads, 8x4 per-thread tile, double-buffered smem.
__global__ __launch_bounds__(256, 2) void gemm1_kernel(
    const float* __restrict__ A,   // [NN, 512]
    const float* __restrict__ B,   // [512, 256]
    const float* __restrict__ bias)
{
    __shared__ float As[2][16][128];   // K-major A tile
    __shared__ float Bs[2][16][64];

    const int tid = threadIdx.x;
    const int tx  = tid & 15;          // 16 col groups (4 cols each)
    const int ty  = tid >> 4;          // 16 row groups (8 rows each)
    const int bm0 = blockIdx.x * 128;
    const int bn0 = blockIdx.y * 64;

    const int arow = tid >> 2;         // 0..63
    const int ak   = (tid & 3) << 2;   // 0,4,8,12
    const int bk   = tid >> 4;         // 0..15
    const int bc   = (tid & 15) << 2;  // 0..60

    const int g0 = bm0 + arow;
    const int g1 = bm0 + arow + 64;

    float acc[8][4];
#pragma unroll
    for (int i = 0; i < 8; i++)
#pragma unroll
        for (int j = 0; j < 4; j++) acc[i][j] = 0.0f;

    float4 ra0, ra1, rb;
    const float4 z4 = make_float4(0.f, 0.f, 0.f, 0.f);

    // prologue: tile 0
    ra0 = (g0 < NN) ? *(const float4*)(A + (size_t)g0 * IND + ak) : z4;
    ra1 = (g1 < NN) ? *(const float4*)(A + (size_t)g1 * IND + ak) : z4;
    rb  = *(const float4*)(B + (size_t)bk * HIDD + bn0 + bc);

    As[0][ak + 0][arow] = ra0.x; As[0][ak + 1][arow] = ra0.y;
    As[0][ak + 2][arow] = ra0.z; As[0][ak + 3][arow] = ra0.w;
    As[0][ak + 0][arow + 64] = ra1.x; As[0][ak + 1][arow + 64] = ra1.y;
    As[0][ak + 2][arow + 64] = ra1.z; As[0][ak + 3][arow + 64] = ra1.w;
    *(float4*)&Bs[0][bk][bc] = rb;
    __syncthreads();

    int buf = 0;
    const int NKT = IND / 16;   // 32
    for (int kt = 0; kt < NKT; kt++) {
        if (kt + 1 < NKT) {
            const int ko = (kt + 1) * 16;
            ra0 = (g0 < NN) ? *(const float4*)(A + (size_t)g0 * IND + ko + ak) : z4;
            ra1 = (g1 < NN) ? *(const float4*)(A + (size_t)g1 * IND + ko + ak) : z4;
            rb  = *(const float4*)(B + (size_t)(ko + bk) * HIDD + bn0 + bc);
        }
#pragma unroll
        for (int k = 0; k < 16; k++) {
            float4 a0 = *(const float4*)&As[buf][k][ty * 8];
            float4 a1 = *(const float4*)&As[buf][k][ty * 8 + 4];
            float4 b4 = *(const float4*)&Bs[buf][k][tx * 4];
            float av[8] = {a0.x, a0.y, a0.z, a0.w, a1.x, a1.y, a1.z, a1.w};
            float bv[4] = {b4.x, b4.y, b4.z, b4.w};
#pragma unroll
            for (int i = 0; i < 8; i++)
#pragma unroll
                for (int j = 0; j < 4; j++)
                    acc[i][j] = fmaf(av[i], bv[j], acc[i][j]);
        }
        if (kt + 1 < NKT) {
            const int nb = buf ^ 1;
            As[nb][ak + 0][arow] = ra0.x; As[nb][ak + 1][arow] = ra0.y;
            As[nb][ak + 2][arow] = ra0.z; As[nb][ak + 3][arow] = ra0.w;
            As[nb][ak + 0][arow + 64] = ra1.x; As[nb][ak + 1][arow + 64] = ra1.y;
            As[nb][ak + 2][arow + 64] = ra1.z; As[nb][ak + 3][arow + 64] = ra1.w;
            *(float4*)&Bs[nb][bk][bc] = rb;
            __syncthreads();
            buf = nb;
        }
    }

    // epilogue: bias + relu
    const int gc = bn0 + tx * 4;
    const float bb0 = bias[gc], bb1 = bias[gc + 1], bb2 = bias[gc + 2], bb3 = bias[gc + 3];
#pragma unroll
    for (int i = 0; i < 8; i++) {
        const int gr = bm0 + ty * 8 + i;
        if (gr < NN) {
            float4 o;
            o.x = fmaxf(acc[i][0] + bb0, 0.f);
            o.y = fmaxf(acc[i][1] + bb1, 0.f);
            o.z = fmaxf(acc[i][2] + bb2, 0.f);
            o.w = fmaxf(acc[i][3] + bb3, 0.f);
            *(float4*)(g_h1 + (size_t)gr * HIDD + gc) = o;
        }
    }
}

// ---------------- GEMM2 + fused epilogue ----------------
// h0 = h1 @ W2 + b2 ; hs = h0 * norm_out ; agg = 0
// Block: 256 rows; thread = (4 rows) x (12 cols). W2^T cached in smem (48 KB).
__global__ __launch_bounds__(256) void gemm2_kernel(
    const float* __restrict__ W2,   // [256, 48]
    const float* __restrict__ b2)
{
    __shared__ float Ws[OD][HIDD];  // Ws[c][k] = W2[k][c]   (48*256*4 = 48 KB)

    const int tid = threadIdx.x;
    for (int i = tid; i < OD * HIDD; i += 256) {
        const int c = i >> 8;
        const int k = i & 255;
        Ws[c][k] = W2[(size_t)k * OD + c];
    }
    __syncthreads();

    const int c0 = (tid & 3) * 12;
    const int r0 = blockIdx.x * 256 + (tid >> 2) * 4;

    float acc[4][12];
#pragma unroll
    for (int r = 0; r < 4; r++)
#pragma unroll
        for (int c = 0; c < 12; c++) acc[r][c] = 0.0f;

    const float4 z4 = make_float4(0.f, 0.f, 0.f, 0.f);
    for (int k4 = 0; k4 < HIDD / 4; k4++) {
        float4 a[4];
#pragma unroll
        for (int r = 0; r < 4; r++) {
            const int row = r0 + r;
            a[r] = (row < NN) ? *(const float4*)(g_h1 + (size_t)row * HIDD + k4 * 4) : z4;
        }
#pragma unroll
        for (int c = 0; c < 12; c++) {
            float4 w = *(const float4*)&Ws[c0 + c][k4 * 4];
#pragma unroll
            for (int r = 0; r < 4; r++) {
                acc[r][c] = fmaf(a[r].x, w.x, acc[r][c]);
                acc[r][c] = fmaf(a[r].y, w.y, acc[r][c]);
                acc[r][c] = fmaf(a[r].z, w.z, acc[r][c]);
                acc[r][c] = fmaf(a[r].w, w.w, acc[r][c]);
            }
        }
    }

    float bb[12];
#pragma unroll
    for (int c = 0; c < 12; c++) bb[c] = b2[c0 + c];

#pragma unroll
    for (int r = 0; r < 4; r++) {
        const int row = r0 + r;
        if (row < NN) {
            const float no = g_no[row];
            const size_t base = (size_t)row * OD + c0;
            float v[12];
#pragma unroll
            for (int c = 0; c < 12; c++) v[c] = acc[r][c] + bb[c];
#pragma unroll
            for (int q = 0; q < 3; q++) {
                float4 h0v = make_float4(v[q*4], v[q*4+1], v[q*4+2], v[q*4+3]);
                float4 hsv = make_float4(h0v.x*no, h0v.y*no, h0v.z*no, h0v.w*no);
                *(float4*)(g_h0 + base + q * 4)  = h0v;
                *(float4*)(g_hs + base + q * 4)  = hsv;
                *(float4*)(g_agg + base + q * 4) = make_float4(0.f, 0.f, 0.f, 0.f);
            }
        }
    }
}

// ---------------- edge scatter: agg[dst] += hs[src] ----------------
__global__ __launch_bounds__(256) void scatter_kernel(
    const int* __restrict__ src, const int* __restrict__ dst)
{
    const int e = blockIdx.x * 256 + threadIdx.x;
    if (e >= EE) return;
    const float* s = g_hs + (size_t)src[e] * OD;
    float*       d = g_agg + (size_t)dst[e] * OD;
#pragma unroll
    for (int c = 0; c < 12; c++) {
        float4 v = *(const float4*)(s + c * 4);
        asm volatile("red.global.add.v4.f32 [%0], {%1,%2,%3,%4};"
                     :: "l"(d + c * 4), "f"(v.x), "f"(v.y), "f"(v.z), "f"(v.w)
                     : "memory");
    }
}

// ---------------- update: t = 0.9*ni*agg + 0.1*h0 ; hs=t*no ; agg=0 (or out=t) ----------------
__global__ __launch_bounds__(256) void update_kernel(float* __restrict__ out, int isFinal)
{
    const int idx = blockIdx.x * 256 + threadIdx.x;   // over NN*12 float4s
    if (idx >= NN * 12) return;
    const int row = idx / 12;

    float4 a = ((const float4*)g_agg)[idx];
    float4 h = ((const float4*)g_h0)[idx];
    const float ni = g_ni[row] * 0.9f;
    float4 t;
    t.x = fmaf(a.x, ni, 0.1f * h.x);
    t.y = fmaf(a.y, ni, 0.1f * h.y);
    t.z = fmaf(a.z, ni, 0.1f * h.z);
    t.w = fmaf(a.w, ni, 0.1f * h.w);

    if (isFinal) {
        ((float4*)out)[idx] = t;
    } else {
        const float no = g_no[row];
        ((float4*)g_hs)[idx]  = make_float4(t.x * no, t.y * no, t.z * no, t.w * no);
        ((float4*)g_agg)[idx] = make_float4(0.f, 0.f, 0.f, 0.f);
    }
}

// ---------------- launch ----------------
extern "C" void kernel_launch(void* const* d_in, const int* in_sizes, int n_in,
                              void* d_out, int out_size)
{
    const float* feats = (const float*)d_in[0];
    const int*   src   = (const int*)d_in[1];
    const int*   dst   = (const int*)d_in[2];
    const float* W1    = (const float*)d_in[3];
    const float* b1    = (const float*)d_in[4];
    const float* W2    = (const float*)d_in[5];
    const float* b2    = (const float*)d_in[6];
    float* out = (float*)d_out;
    (void)in_sizes; (void)n_in; (void)out_size;

    zero_deg_kernel<<<(2 * NN + 255) / 256, 256>>>();
    count_deg_kernel<<<(EE + 255) / 256, 256>>>(src, dst);
    norm_kernel<<<(NN + 255) / 256, 256>>>();

    dim3 grid1((NN + 127) / 128, HIDD / 64);
    gemm1_kernel<<<grid1, 256>>>(feats, W1, b1);
    gemm2_kernel<<<(NN + 255) / 256, 256>>>(W2, b2);

    for (int k = 0; k < KIT; k++) {
        scatter_kernel<<<(EE + 255) / 256, 256>>>(src, dst);
        update_kernel<<<(NN * 12 + 255) / 256, 256>>>(out, (k == KIT - 1) ? 1 : 0);
    }
}

// round 2
// speedup vs baseline: 1.9759x; 1.9759x over previous
#include <cuda_runtime.h>
#include <cstdint>

#define NN   100000
#define EE   1600000
#define IND  512
#define HIDD 256
#define OD   48
#define KIT  10

#define SB   512
#define NBLK ((NN + SB - 1) / SB)   // 196

// ---------------- scratch ----------------
__device__ float g_h1[(size_t)NN * HIDD];   // MLP hidden
__device__ float g_h0[(size_t)NN * OD];     // teleport anchor
__device__ float g_hsA[(size_t)NN * OD];    // ping
__device__ float g_hsB[(size_t)NN * OD];    // pong
__device__ float g_no[NN];
__device__ float g_ni[NN];
__device__ int   g_deg[2 * NN];             // [0..NN) out-deg, [NN..2NN) in-deg
__device__ int   g_rs[NN + 1];              // CSR row starts (by dst)
__device__ int   g_cur[NN];
__device__ int   g_csrc[EE];                // src ids grouped by dst
__device__ int   g_part[NBLK];
__device__ int   g_ppre[NBLK + 1];

// ---------------- degrees ----------------
__global__ void zero_deg_kernel() {
    int i = blockIdx.x * blockDim.x + threadIdx.x;
    if (i < 2 * NN) g_deg[i] = 0;
}

__global__ void count_deg_kernel(const int* __restrict__ src, const int* __restrict__ dst) {
    int e = blockIdx.x * blockDim.x + threadIdx.x;
    if (e < EE) {
        atomicAdd(&g_deg[src[e]], 1);
        atomicAdd(&g_deg[NN + dst[e]], 1);
    }
}

__global__ void norm_kernel() {
    int i = blockIdx.x * blockDim.x + threadIdx.x;
    if (i < NN) {
        g_no[i] = rsqrtf(fmaxf((float)g_deg[i], 1.0f));
        g_ni[i] = rsqrtf(fmaxf((float)g_deg[NN + i], 1.0f));
    }
    if (i == 0) g_rs[NN] = EE;
}

// ---------------- CSR build: scan of in-degrees ----------------
__global__ __launch_bounds__(SB) void scan1_kernel() {
    __shared__ int s[SB];
    const int tid = threadIdx.x;
    const int i = blockIdx.x * SB + tid;
    s[tid] = (i < NN) ? g_deg[NN + i] : 0;
    __syncthreads();
#pragma unroll
    for (int o = SB / 2; o > 0; o >>= 1) {
        if (tid < o) s[tid] += s[tid + o];
        __syncthreads();
    }
    if (tid == 0) g_part[blockIdx.x] = s[0];
}

__global__ void scan2_kernel() {   // <<<1,1>>> serial over 196 partials
    int r = 0;
    for (int b = 0; b < NBLK; b++) { g_ppre[b] = r; r += g_part[b]; }
    g_ppre[NBLK] = r;
}

__global__ __launch_bounds__(SB) void scan3_kernel() {
    __shared__ int s[SB];
    const int tid = threadIdx.x;
    const int i = blockIdx.x * SB + tid;
    const int v = (i < NN) ? g_deg[NN + i] : 0;
    s[tid] = v;
    __syncthreads();
#pragma unroll
    for (int o = 1; o < SB; o <<= 1) {
        int x = (tid >= o) ? s[tid - o] : 0;
        __syncthreads();
        s[tid] += x;
        __syncthreads();
    }
    if (i < NN) {
        g_rs[i] = g_ppre[blockIdx.x] + s[tid] - v;   // exclusive
        g_cur[i] = 0;
    }
}

__global__ __launch_bounds__(256) void fill_kernel(const int* __restrict__ src,
                                                   const int* __restrict__ dst) {
    const int e = blockIdx.x * 256 + threadIdx.x;
    if (e < EE) {
        const int d = dst[e];
        const int pos = atomicAdd(&g_cur[d], 1);
        g_csrc[g_rs[d] + pos] = src[e];
    }
}

// ---------------- GEMM1: h1 = relu(feats @ W1 + b1) ----------------
// 128x128 block tile, BK=16, 256 threads, 8x8 per-thread, double-buffered smem.
__global__ __launch_bounds__(256) void gemm1_kernel(
    const float* __restrict__ A,   // [NN, 512]
    const float* __restrict__ B,   // [512, 256]
    const float* __restrict__ bias)
{
    __shared__ float As[2][16][128];
    __shared__ float Bs[2][16][128];

    const int tid = threadIdx.x;
    const int bm0 = blockIdx.x * 128;
    const int bn0 = blockIdx.y * 128;
    const int tx = tid & 15, ty = tid >> 4;

    const int arow = tid >> 1;          // 0..127
    const int ak0  = (tid & 1) * 8;     // 0 or 8
    const int bk   = tid >> 4;          // 0..15
    const int bn   = (tid & 15) * 8;    // 0..120

    const int ga = bm0 + arow;
    const bool av = ga < NN;
    const float4 z4 = make_float4(0.f, 0.f, 0.f, 0.f);

    float acc[8][8];
#pragma unroll
    for (int i = 0; i < 8; i++)
#pragma unroll
        for (int j = 0; j < 8; j++) acc[i][j] = 0.f;

    float4 pa0, pa1, pb0, pb1;

    // tile 0
    pa0 = av ? *(const float4*)(A + (size_t)ga * IND + ak0)     : z4;
    pa1 = av ? *(const float4*)(A + (size_t)ga * IND + ak0 + 4) : z4;
    pb0 = *(const float4*)(B + (size_t)bk * HIDD + bn0 + bn);
    pb1 = *(const float4*)(B + (size_t)bk * HIDD + bn0 + bn + 4);

    As[0][ak0 + 0][arow] = pa0.x; As[0][ak0 + 1][arow] = pa0.y;
    As[0][ak0 + 2][arow] = pa0.z; As[0][ak0 + 3][arow] = pa0.w;
    As[0][ak0 + 4][arow] = pa1.x; As[0][ak0 + 5][arow] = pa1.y;
    As[0][ak0 + 6][arow] = pa1.z; As[0][ak0 + 7][arow] = pa1.w;
    *(float4*)&Bs[0][bk][bn]     = pb0;
    *(float4*)&Bs[0][bk][bn + 4] = pb1;
    __syncthreads();

    int buf = 0;
    const int NKT = IND / 16;   // 32
    for (int kt = 0; kt < NKT; kt++) {
        if (kt + 1 < NKT) {
            const int ko = (kt + 1) * 16;
            pa0 = av ? *(const float4*)(A + (size_t)ga * IND + ko + ak0)     : z4;
            pa1 = av ? *(const float4*)(A + (size_t)ga * IND + ko + ak0 + 4) : z4;
            pb0 = *(const float4*)(B + (size_t)(ko + bk) * HIDD + bn0 + bn);
            pb1 = *(const float4*)(B + (size_t)(ko + bk) * HIDD + bn0 + bn + 4);
        }
#pragma unroll
        for (int k = 0; k < 16; k++) {
            float4 a0 = *(const float4*)&As[buf][k][ty * 8];
            float4 a1 = *(const float4*)&As[buf][k][ty * 8 + 4];
            float4 b0 = *(const float4*)&Bs[buf][k][tx * 8];
            float4 b1 = *(const float4*)&Bs[buf][k][tx * 8 + 4];
            float av8[8] = {a0.x, a0.y, a0.z, a0.w, a1.x, a1.y, a1.z, a1.w};
            float bv8[8] = {b0.x, b0.y, b0.z, b0.w, b1.x, b1.y, b1.z, b1.w};
#pragma unroll
            for (int i = 0; i < 8; i++)
#pragma unroll
                for (int j = 0; j < 8; j++)
                    acc[i][j] = fmaf(av8[i], bv8[j], acc[i][j]);
        }
        if (kt + 1 < NKT) {
            const int nb = buf ^ 1;
            As[nb][ak0 + 0][arow] = pa0.x; As[nb][ak0 + 1][arow] = pa0.y;
            As[nb][ak0 + 2][arow] = pa0.z; As[nb][ak0 + 3][arow] = pa0.w;
            As[nb][ak0 + 4][arow] = pa1.x; As[nb][ak0 + 5][arow] = pa1.y;
            As[nb][ak0 + 6][arow] = pa1.z; As[nb][ak0 + 7][arow] = pa1.w;
            *(float4*)&Bs[nb][bk][bn]     = pb0;
            *(float4*)&Bs[nb][bk][bn + 4] = pb1;
            __syncthreads();
            buf = nb;
        }
    }

    // epilogue: bias + relu
    const int gc = bn0 + tx * 8;
    float4 bb0 = *(const float4*)(bias + gc);
    float4 bb1 = *(const float4*)(bias + gc + 4);
    const float bv8[8] = {bb0.x, bb0.y, bb0.z, bb0.w, bb1.x, bb1.y, bb1.z, bb1.w};
#pragma unroll
    for (int i = 0; i < 8; i++) {
        const int gr = bm0 + ty * 8 + i;
        if (gr < NN) {
            float4 o0, o1;
            o0.x = fmaxf(acc[i][0] + bv8[0], 0.f);
            o0.y = fmaxf(acc[i][1] + bv8[1], 0.f);
            o0.z = fmaxf(acc[i][2] + bv8[2], 0.f);
            o0.w = fmaxf(acc[i][3] + bv8[3], 0.f);
            o1.x = fmaxf(acc[i][4] + bv8[4], 0.f);
            o1.y = fmaxf(acc[i][5] + bv8[5], 0.f);
            o1.z = fmaxf(acc[i][6] + bv8[6], 0.f);
            o1.w = fmaxf(acc[i][7] + bv8[7], 0.f);
            *(float4*)(g_h1 + (size_t)gr * HIDD + gc)     = o0;
            *(float4*)(g_h1 + (size_t)gr * HIDD + gc + 4) = o1;
        }
    }
}

// ---------------- GEMM2 + fused epilogue: h0, hsA = h0*no ----------------
__global__ __launch_bounds__(256) void gemm2_kernel(
    const float* __restrict__ W2,   // [256, 48]
    const float* __restrict__ b2)
{
    __shared__ float Ws[OD][HIDD];  // 48 KB, transposed

    const int tid = threadIdx.x;
    for (int i = tid; i < OD * HIDD; i += 256) {
        const int c = i >> 8;
        const int k = i & 255;
        Ws[c][k] = W2[(size_t)k * OD + c];
    }
    __syncthreads();

    const int c0 = (tid & 3) * 12;
    const int r0 = blockIdx.x * 256 + (tid >> 2) * 4;

    float acc[4][12];
#pragma unroll
    for (int r = 0; r < 4; r++)
#pragma unroll
        for (int c = 0; c < 12; c++) acc[r][c] = 0.f;

    const float4 z4 = make_float4(0.f, 0.f, 0.f, 0.f);
    for (int k4 = 0; k4 < HIDD / 4; k4++) {
        float4 a[4];
#pragma unroll
        for (int r = 0; r < 4; r++) {
            const int row = r0 + r;
            a[r] = (row < NN) ? *(const float4*)(g_h1 + (size_t)row * HIDD + k4 * 4) : z4;
        }
#pragma unroll
        for (int c = 0; c < 12; c++) {
            float4 w = *(const float4*)&Ws[c0 + c][k4 * 4];
#pragma unroll
            for (int r = 0; r < 4; r++) {
                acc[r][c] = fmaf(a[r].x, w.x, acc[r][c]);
                acc[r][c] = fmaf(a[r].y, w.y, acc[r][c]);
                acc[r][c] = fmaf(a[r].z, w.z, acc[r][c]);
                acc[r][c] = fmaf(a[r].w, w.w, acc[r][c]);
            }
        }
    }

    float bb[12];
#pragma unroll
    for (int c = 0; c < 12; c++) bb[c] = b2[c0 + c];

#pragma unroll
    for (int r = 0; r < 4; r++) {
        const int row = r0 + r;
        if (row < NN) {
            const float no = g_no[row];
            const size_t base = (size_t)row * OD + c0;
#pragma unroll
            for (int q = 0; q < 3; q++) {
                float4 h0v = make_float4(acc[r][q*4] + bb[q*4], acc[r][q*4+1] + bb[q*4+1],
                                         acc[r][q*4+2] + bb[q*4+2], acc[r][q*4+3] + bb[q*4+3]);
                *(float4*)(g_h0 + base + q * 4)  = h0v;
                *(float4*)(g_hsA + base + q * 4) = make_float4(h0v.x*no, h0v.y*no, h0v.z*no, h0v.w*no);
            }
        }
    }
}

// ---------------- fused propagate iteration ----------------
// 4 threads per node. Thread p owns float4 chunks {p, p+4, p+8} of the 12-chunk row
// (so each of the 3 load instructions is a coalesced 64B read within the group).
// acc = sum_{in-edges} hs_cur[src]; t = 0.9*ni*acc + 0.1*h0;
// write out (final) or hs_next = t*no.
__global__ __launch_bounds__(256) void prop_kernel(int useB, float* __restrict__ out, int isFinal)
{
    const int t = blockIdx.x * 256 + threadIdx.x;
    if (t >= NN * 4) return;
    const int node = t >> 2;
    const int p = t & 3;

    const float* __restrict__ cur = useB ? g_hsB : g_hsA;
    float* __restrict__ nxt       = useB ? g_hsA : g_hsB;

    const int rs = g_rs[node];
    const int re = g_rs[node + 1];

    float4 a0 = make_float4(0.f, 0.f, 0.f, 0.f);
    float4 a1 = a0, a2 = a0;

    for (int i = rs; i < re; i++) {
        const size_t b = (size_t)g_csrc[i] * OD;
        const float4 v0 = *(const float4*)(cur + b + (p    ) * 4);
        const float4 v1 = *(const float4*)(cur + b + (p + 4) * 4);
        const float4 v2 = *(const float4*)(cur + b + (p + 8) * 4);
        a0.x += v0.x; a0.y += v0.y; a0.z += v0.z; a0.w += v0.w;
        a1.x += v1.x; a1.y += v1.y; a1.z += v1.z; a1.w += v1.w;
        a2.x += v2.x; a2.y += v2.y; a2.z += v2.z; a2.w += v2.w;
    }

    const float ni9 = 0.9f * g_ni[node];
    const size_t ob = (size_t)node * OD;
    const float4 h0 = *(const float4*)(g_h0 + ob + (p    ) * 4);
    const float4 h1 = *(const float4*)(g_h0 + ob + (p + 4) * 4);
    const float4 h2 = *(const float4*)(g_h0 + ob + (p + 8) * 4);

    float4 t0, t1, t2;
    t0.x = fmaf(a0.x, ni9, 0.1f * h0.x); t0.y = fmaf(a0.y, ni9, 0.1f * h0.y);
    t0.z = fmaf(a0.z, ni9, 0.1f * h0.z); t0.w = fmaf(a0.w, ni9, 0.1f * h0.w);
    t1.x = fmaf(a1.x, ni9, 0.1f * h1.x); t1.y = fmaf(a1.y, ni9, 0.1f * h1.y);
    t1.z = fmaf(a1.z, ni9, 0.1f * h1.z); t1.w = fmaf(a1.w, ni9, 0.1f * h1.w);
    t2.x = fmaf(a2.x, ni9, 0.1f * h2.x); t2.y = fmaf(a2.y, ni9, 0.1f * h2.y);
    t2.z = fmaf(a2.z, ni9, 0.1f * h2.z); t2.w = fmaf(a2.w, ni9, 0.1f * h2.w);

    if (isFinal) {
        *(float4*)(out + ob + (p    ) * 4) = t0;
        *(float4*)(out + ob + (p + 4) * 4) = t1;
        *(float4*)(out + ob + (p + 8) * 4) = t2;
    } else {
        const float no = g_no[node];
        *(float4*)(nxt + ob + (p    ) * 4) = make_float4(t0.x*no, t0.y*no, t0.z*no, t0.w*no);
        *(float4*)(nxt + ob + (p + 4) * 4) = make_float4(t1.x*no, t1.y*no, t1.z*no, t1.w*no);
        *(float4*)(nxt + ob + (p + 8) * 4) = make_float4(t2.x*no, t2.y*no, t2.z*no, t2.w*no);
    }
}

// ---------------- launch ----------------
extern "C" void kernel_launch(void* const* d_in, const int* in_sizes, int n_in,
                              void* d_out, int out_size)
{
    const float* feats = (const float*)d_in[0];
    const int*   src   = (const int*)d_in[1];
    const int*   dst   = (const int*)d_in[2];
    const float* W1    = (const float*)d_in[3];
    const float* b1    = (const float*)d_in[4];
    const float* W2    = (const float*)d_in[5];
    const float* b2    = (const float*)d_in[6];
    float* out = (float*)d_out;
    (void)in_sizes; (void)n_in; (void)out_size;

    zero_deg_kernel<<<(2 * NN + 255) / 256, 256>>>();
    count_deg_kernel<<<(EE + 255) / 256, 256>>>(src, dst);
    norm_kernel<<<(NN + 255) / 256, 256>>>();

    scan1_kernel<<<NBLK, SB>>>();
    scan2_kernel<<<1, 1>>>();
    scan3_kernel<<<NBLK, SB>>>();
    fill_kernel<<<(EE + 255) / 256, 256>>>(src, dst);

    dim3 grid1((NN + 127) / 128, HIDD / 128);
    gemm1_kernel<<<grid1, 256>>>(feats, W1, b1);
    gemm2_kernel<<<(NN + 255) / 256, 256>>>(W2, b2);

    for (int k = 0; k < KIT; k++) {
        prop_kernel<<<(NN * 4 + 255) / 256, 256>>>(k & 1, out, (k == KIT - 1) ? 1 : 0);
    }
}

// round 5
// speedup vs baseline: 2.6597x; 1.3461x over previous
#include <cuda_runtime.h>
#include <cuda_bf16.h>
#include <cstdint>

#define NN   100000
#define EE   1600000
#define IND  512
#define HIDD 256
#define OD   48
#define KIT  10

#define SB   512
#define NBLK ((NN + SB - 1) / SB)   // 196

// ---------------- scratch ----------------
__device__ float g_h1[(size_t)NN * HIDD];
__device__ float g_h0[(size_t)NN * OD];
__device__ float g_hsA[(size_t)NN * OD];
__device__ float g_hsB[(size_t)NN * OD];
__device__ float g_no[NN];
__device__ float g_ni[NN];
__device__ int   g_deg[2 * NN];
__device__ int   g_rs[NN + 1];
__device__ int   g_cur[NN];
__device__ int   g_csrc[EE];
__device__ int   g_part[NBLK];
__device__ int   g_ppre[NBLK + 1];
__device__ int   g_bin[64];
__device__ int   g_binoff[65];
__device__ int   g_bincur[64];
__device__ int   g_ord[NN];

// ---------------- degrees ----------------
__global__ void zero_deg_kernel() {
    int i = blockIdx.x * blockDim.x + threadIdx.x;
    if (i < 2 * NN) g_deg[i] = 0;
    if (i < 64) { g_bin[i] = 0; g_bincur[i] = 0; }
}
__global__ void count_deg_kernel(const int* __restrict__ src, const int* __restrict__ dst) {
    int e = blockIdx.x * blockDim.x + threadIdx.x;
    if (e < EE) {
        atomicAdd(&g_deg[src[e]], 1);
        atomicAdd(&g_deg[NN + dst[e]], 1);
    }
}
__global__ void norm_kernel() {
    int i = blockIdx.x * blockDim.x + threadIdx.x;
    if (i < NN) {
        g_no[i] = rsqrtf(fmaxf((float)g_deg[i], 1.0f));
        g_ni[i] = rsqrtf(fmaxf((float)g_deg[NN + i], 1.0f));
        int d = g_deg[NN + i]; if (d > 63) d = 63;
        atomicAdd(&g_bin[d], 1);
    }
    if (i == 0) g_rs[NN] = EE;
}

// ---------------- CSR build ----------------
__global__ __launch_bounds__(SB) void scan1_kernel() {
    __shared__ int s[SB];
    const int tid = threadIdx.x;
    const int i = blockIdx.x * SB + tid;
    s[tid] = (i < NN) ? g_deg[NN + i] : 0;
    __syncthreads();
#pragma unroll
    for (int o = SB / 2; o > 0; o >>= 1) {
        if (tid < o) s[tid] += s[tid + o];
        __syncthreads();
    }
    if (tid == 0) g_part[blockIdx.x] = s[0];
}
__global__ void scan2_kernel() {
    int r = 0;
    for (int b = 0; b < NBLK; b++) { g_ppre[b] = r; r += g_part[b]; }
    g_ppre[NBLK] = r;
    int r2 = 0;
    for (int b = 0; b < 64; b++) { g_binoff[b] = r2; r2 += g_bin[b]; }
    g_binoff[64] = r2;
}
__global__ __launch_bounds__(SB) void scan3_kernel() {
    __shared__ int s[SB];
    const int tid = threadIdx.x;
    const int i = blockIdx.x * SB + tid;
    const int v = (i < NN) ? g_deg[NN + i] : 0;
    s[tid] = v;
    __syncthreads();
#pragma unroll
    for (int o = 1; o < SB; o <<= 1) {
        int x = (tid >= o) ? s[tid - o] : 0;
        __syncthreads();
        s[tid] += x;
        __syncthreads();
    }
    if (i < NN) {
        g_rs[i] = g_ppre[blockIdx.x] + s[tid] - v;
        g_cur[i] = 0;
    }
}
__global__ __launch_bounds__(256) void fill_kernel(const int* __restrict__ src,
                                                   const int* __restrict__ dst) {
    const int e = blockIdx.x * 256 + threadIdx.x;
    if (e < EE) {
        const int d = dst[e];
        const int pos = atomicAdd(&g_cur[d], 1);
        g_csrc[g_rs[d] + pos] = src[e];
    }
}
__global__ __launch_bounds__(256) void binfill_kernel() {
    const int i = blockIdx.x * 256 + threadIdx.x;
    if (i < NN) {
        int d = g_deg[NN + i]; if (d > 63) d = 63;
        const int pos = atomicAdd(&g_bincur[d], 1);
        g_ord[g_binoff[d] + pos] = i;
    }
}

// ---------------- GEMM1 via mma.sync bf16 (3-pass split) ----------------
// C = relu(A[100000,512] @ W1[512,256] + b1). CTA tile 128x128, BK=32, 8 warps (4x2).
// smem (per stage): Ahi[128][80B] Alo Bhi[32][272B] Blo. Double buffered.
#define A_STRIDE 80
#define A_TILE   (128 * A_STRIDE)           // 10240
#define B_STRIDE 272
#define B_TILE   (32 * B_STRIDE)            // 8704
#define STAGE_BYTES (2 * A_TILE + 2 * B_TILE)   // 37888
#define SMEM_G1  (2 * STAGE_BYTES)              // 75776

__device__ __forceinline__ uint32_t smem_u32(const void* p) {
    uint32_t a;
    asm("{ .reg .u64 t; cvta.to.shared.u64 t, %1; cvt.u32.u64 %0, t; }" : "=r"(a) : "l"(p));
    return a;
}
__device__ __forceinline__ uint32_t pack_bf(float x, float y) {
    __nv_bfloat162 t = __floats2bfloat162_rn(x, y);
    return *reinterpret_cast<uint32_t*>(&t);
}
__device__ __forceinline__ void split4(float4 v, uint2& hi, uint2& lo) {
    float hx = __bfloat162float(__float2bfloat16_rn(v.x));
    float hy = __bfloat162float(__float2bfloat16_rn(v.y));
    float hz = __bfloat162float(__float2bfloat16_rn(v.z));
    float hw = __bfloat162float(__float2bfloat16_rn(v.w));
    hi.x = pack_bf(v.x, v.y);
    hi.y = pack_bf(v.z, v.w);
    lo.x = pack_bf(v.x - hx, v.y - hy);
    lo.y = pack_bf(v.z - hz, v.w - hw);
}

#define LDSM4(R, addr)                                                          \
    asm volatile("ldmatrix.sync.aligned.m8n8.x4.shared.b16 {%0,%1,%2,%3}, [%4];" \
                 : "=r"((R)[0]), "=r"((R)[1]), "=r"((R)[2]), "=r"((R)[3]) : "r"(addr))
#define LDSM4T(R, addr)                                                              \
    asm volatile("ldmatrix.sync.aligned.m8n8.x4.trans.shared.b16 {%0,%1,%2,%3}, [%4];" \
                 : "=r"((R)[0]), "=r"((R)[1]), "=r"((R)[2]), "=r"((R)[3]) : "r"(addr))
#define MMA16816(D, Af, B0, B1)                                                  \
    asm volatile("mma.sync.aligned.m16n8k16.row.col.f32.bf16.bf16.f32 "          \
                 "{%0,%1,%2,%3}, {%4,%5,%6,%7}, {%8,%9}, {%0,%1,%2,%3};"         \
                 : "+f"((D)[0]), "+f"((D)[1]), "+f"((D)[2]), "+f"((D)[3])        \
                 : "r"((Af)[0]), "r"((Af)[1]), "r"((Af)[2]), "r"((Af)[3]),       \
                   "r"(B0), "r"(B1))

__global__ __launch_bounds__(256, 1) void gemm1_mma_kernel(
    const float* __restrict__ A, const float* __restrict__ W1,
    const float* __restrict__ bias)
{
    extern __shared__ char smem[];
    const uint32_t sbase = smem_u32(smem);
    const int tid = threadIdx.x;
    const int lane = tid & 31;
    const int wid = tid >> 5;
    const int warp_m = wid & 3;       // 4 m-warps * 32 rows
    const int warp_n = wid >> 2;      // 2 n-warps * 64 cols
    const int bm0 = blockIdx.x * 128;
    const int bn0 = blockIdx.y * 128;

    const float4 z4 = make_float4(0.f, 0.f, 0.f, 0.f);
    float d[2][8][4];
#pragma unroll
    for (int mi = 0; mi < 2; mi++)
#pragma unroll
        for (int ni = 0; ni < 8; ni++)
#pragma unroll
            for (int q = 0; q < 4; q++) d[mi][ni][q] = 0.f;

    float4 pa[4], pb[4];

    // A load map: idx = tid + i*256 over 1024 float4; row = idx>>3, c4 = idx&7
    // B load map: row(k) = idx>>5, n4 = idx&31
#define LOAD_STAGE(k0)                                                              \
    {                                                                               \
        _Pragma("unroll") for (int i = 0; i < 4; i++) {                             \
            const int idx = tid + i * 256;                                          \
            const int row = idx >> 3, c4 = idx & 7;                                 \
            const int gr = bm0 + row;                                               \
            pa[i] = (gr < NN) ? *(const float4*)(A + (size_t)gr * IND + (k0) + c4 * 4) : z4; \
        }                                                                           \
        _Pragma("unroll") for (int i = 0; i < 4; i++) {                             \
            const int idx = tid + i * 256;                                          \
            const int row = idx >> 5, n4 = idx & 31;                                \
            pb[i] = *(const float4*)(W1 + (size_t)((k0) + row) * HIDD + bn0 + n4 * 4); \
        }                                                                           \
    }

#define STORE_STAGE(s)                                                              \
    {                                                                               \
        char* base = smem + (size_t)(s) * STAGE_BYTES;                              \
        _Pragma("unroll") for (int i = 0; i < 4; i++) {                             \
            const int idx = tid + i * 256;                                          \
            const int row = idx >> 3, c4 = idx & 7;                                 \
            uint2 hi, lo; split4(pa[i], hi, lo);                                    \
            *(uint2*)(base + row * A_STRIDE + c4 * 8) = hi;                         \
            *(uint2*)(base + A_TILE + row * A_STRIDE + c4 * 8) = lo;                \
        }                                                                           \
        _Pragma("unroll") for (int i = 0; i < 4; i++) {                             \
            const int idx = tid + i * 256;                                          \
            const int row = idx >> 5, n4 = idx & 31;                                \
            uint2 hi, lo; split4(pb[i], hi, lo);                                    \
            *(uint2*)(base + 2 * A_TILE + row * B_STRIDE + n4 * 8) = hi;            \
            *(uint2*)(base + 2 * A_TILE + B_TILE + row * B_STRIDE + n4 * 8) = lo;   \
        }                                                                           \
    }

    LOAD_STAGE(0);
    STORE_STAGE(0);
    __syncthreads();

    const uint32_t laneA = (uint32_t)((lane & 15) * A_STRIDE + (lane >> 4) * 16);
    const uint32_t laneB = (uint32_t)((lane & 15) * B_STRIDE + (lane >> 4) * 16);
    const int NST = IND / 32;   // 16

    for (int s = 0; s < NST; s++) {
        if (s + 1 < NST) LOAD_STAGE((s + 1) * 32);

        const uint32_t aHiB = sbase + (uint32_t)((s & 1) * STAGE_BYTES);
        const uint32_t aLoB = aHiB + A_TILE;
        const uint32_t bHiB = aHiB + 2 * A_TILE;
        const uint32_t bLoB = bHiB + B_TILE;
        const int mrow = warp_m * 32;
        const int nb = warp_n * 64;

#pragma unroll
        for (int ks = 0; ks < 2; ks++) {
            const int kb = ks * 16;
            const uint32_t aoff = (uint32_t)(mrow * A_STRIDE + kb * 2) + laneA;
            uint32_t ahi0[4], ahi1[4], alo0[4], alo1[4];
            LDSM4(ahi0, aHiB + aoff);
            LDSM4(ahi1, aHiB + aoff + 16 * A_STRIDE);
            LDSM4(alo0, aLoB + aoff);
            LDSM4(alo1, aLoB + aoff + 16 * A_STRIDE);

            uint32_t bhi[8][2], blo[8][2];
#pragma unroll
            for (int t = 0; t < 4; t++) {
                const uint32_t boff = (uint32_t)(kb * B_STRIDE + (nb + t * 16) * 2) + laneB;
                uint32_t r[4];
                LDSM4T(r, bHiB + boff);
                bhi[2 * t][0] = r[0]; bhi[2 * t][1] = r[1];
                bhi[2 * t + 1][0] = r[2]; bhi[2 * t + 1][1] = r[3];
                LDSM4T(r, bLoB + boff);
                blo[2 * t][0] = r[0]; blo[2 * t][1] = r[1];
                blo[2 * t + 1][0] = r[2]; blo[2 * t + 1][1] = r[3];
            }
#pragma unroll
            for (int ni = 0; ni < 8; ni++) {
                MMA16816(d[0][ni], ahi0, bhi[ni][0], bhi[ni][1]);
                MMA16816(d[1][ni], ahi1, bhi[ni][0], bhi[ni][1]);
                MMA16816(d[0][ni], ahi0, blo[ni][0], blo[ni][1]);
                MMA16816(d[1][ni], ahi1, blo[ni][0], blo[ni][1]);
                MMA16816(d[0][ni], alo0, bhi[ni][0], bhi[ni][1]);
                MMA16816(d[1][ni], alo1, bhi[ni][0], bhi[ni][1]);
            }
        }
        if (s + 1 < NST) STORE_STAGE((s + 1) & 1);
        __syncthreads();
    }

    // epilogue: bias + relu
#pragma unroll
    for (int ni = 0; ni < 8; ni++) {
        const int c = bn0 + warp_n * 64 + ni * 8 + (lane & 3) * 2;
        const float bb0 = bias[c], bb1 = bias[c + 1];
#pragma unroll
        for (int mi = 0; mi < 2; mi++) {
            const int r0 = bm0 + warp_m * 32 + mi * 16 + (lane >> 2);
            if (r0 < NN) {
                float2 o;
                o.x = fmaxf(d[mi][ni][0] + bb0, 0.f);
                o.y = fmaxf(d[mi][ni][1] + bb1, 0.f);
                *(float2*)(g_h1 + (size_t)r0 * HIDD + c) = o;
            }
            const int r1 = r0 + 8;
            if (r1 < NN) {
                float2 o;
                o.x = fmaxf(d[mi][ni][2] + bb0, 0.f);
                o.y = fmaxf(d[mi][ni][3] + bb1, 0.f);
                *(float2*)(g_h1 + (size_t)r1 * HIDD + c) = o;
            }
        }
    }
}

// ---------------- GEMM2 + fused epilogue: h0, hsA = h0*no ----------------
__global__ __launch_bounds__(256) void gemm2_kernel(
    const float* __restrict__ W2, const float* __restrict__ b2)
{
    __shared__ float Ws[OD][HIDD];

    const int tid = threadIdx.x;
    for (int i = tid; i < OD * HIDD; i += 256) {
        const int c = i >> 8;
        const int k = i & 255;
        Ws[c][k] = W2[(size_t)k * OD + c];
    }
    __syncthreads();

    const int c0 = (tid & 3) * 12;
    const int r0 = blockIdx.x * 256 + (tid >> 2) * 4;

    float acc[4][12];
#pragma unroll
    for (int r = 0; r < 4; r++)
#pragma unroll
        for (int c = 0; c < 12; c++) acc[r][c] = 0.f;

    const float4 z4 = make_float4(0.f, 0.f, 0.f, 0.f);
    for (int k4 = 0; k4 < HIDD / 4; k4++) {
        float4 a[4];
#pragma unroll
        for (int r = 0; r < 4; r++) {
            const int row = r0 + r;
            a[r] = (row < NN) ? *(const float4*)(g_h1 + (size_t)row * HIDD + k4 * 4) : z4;
        }
#pragma unroll
        for (int c = 0; c < 12; c++) {
            float4 w = *(const float4*)&Ws[c0 + c][k4 * 4];
#pragma unroll
            for (int r = 0; r < 4; r++) {
                acc[r][c] = fmaf(a[r].x, w.x, acc[r][c]);
                acc[r][c] = fmaf(a[r].y, w.y, acc[r][c]);
                acc[r][c] = fmaf(a[r].z, w.z, acc[r][c]);
                acc[r][c] = fmaf(a[r].w, w.w, acc[r][c]);
            }
        }
    }

    float bb[12];
#pragma unroll
    for (int c = 0; c < 12; c++) bb[c] = b2[c0 + c];

#pragma unroll
    for (int r = 0; r < 4; r++) {
        const int row = r0 + r;
        if (row < NN) {
            const float no = g_no[row];
            const size_t base = (size_t)row * OD + c0;
#pragma unroll
            for (int q = 0; q < 3; q++) {
                float4 h0v = make_float4(acc[r][q*4] + bb[q*4], acc[r][q*4+1] + bb[q*4+1],
                                         acc[r][q*4+2] + bb[q*4+2], acc[r][q*4+3] + bb[q*4+3]);
                *(float4*)(g_h0 + base + q * 4)  = h0v;
                *(float4*)(g_hsA + base + q * 4) = make_float4(h0v.x*no, h0v.y*no, h0v.z*no, h0v.w*no);
            }
        }
    }
}

// ---------------- fused propagate iteration (degree-ordered) ----------------
__global__ __launch_bounds__(256) void prop_kernel(int useB, float* __restrict__ out, int isFinal)
{
    const int t = blockIdx.x * 256 + threadIdx.x;
    if (t >= NN * 4) return;
    const int node = g_ord[t >> 2];
    const int p = t & 3;

    const float* __restrict__ cur = useB ? g_hsB : g_hsA;
    float* __restrict__ nxt       = useB ? g_hsA : g_hsB;

    const int rs = g_rs[node];
    const int re = g_rs[node + 1];

    float4 a0 = make_float4(0.f, 0.f, 0.f, 0.f);
    float4 a1 = a0, a2 = a0;

    for (int i = rs; i < re; i++) {
        const size_t b = (size_t)g_csrc[i] * OD;
        const float4 v0 = *(const float4*)(cur + b + (p    ) * 4);
        const float4 v1 = *(const float4*)(cur + b + (p + 4) * 4);
        const float4 v2 = *(const float4*)(cur + b + (p + 8) * 4);
        a0.x += v0.x; a0.y += v0.y; a0.z += v0.z; a0.w += v0.w;
        a1.x += v1.x; a1.y += v1.y; a1.z += v1.z; a1.w += v1.w;
        a2.x += v2.x; a2.y += v2.y; a2.z += v2.z; a2.w += v2.w;
    }

    const float ni9 = 0.9f * g_ni[node];
    const size_t ob = (size_t)node * OD;
    const float4 h0 = *(const float4*)(g_h0 + ob + (p    ) * 4);
    const float4 h1 = *(const float4*)(g_h0 + ob + (p + 4) * 4);
    const float4 h2 = *(const float4*)(g_h0 + ob + (p + 8) * 4);

    float4 t0, t1, t2;
    t0.x = fmaf(a0.x, ni9, 0.1f * h0.x); t0.y = fmaf(a0.y, ni9, 0.1f * h0.y);
    t0.z = fmaf(a0.z, ni9, 0.1f * h0.z); t0.w = fmaf(a0.w, ni9, 0.1f * h0.w);
    t1.x = fmaf(a1.x, ni9, 0.1f * h1.x); t1.y = fmaf(a1.y, ni9, 0.1f * h1.y);
    t1.z = fmaf(a1.z, ni9, 0.1f * h1.z); t1.w = fmaf(a1.w, ni9, 0.1f * h1.w);
    t2.x = fmaf(a2.x, ni9, 0.1f * h2.x); t2.y = fmaf(a2.y, ni9, 0.1f * h2.y);
    t2.z = fmaf(a2.z, ni9, 0.1f * h2.z); t2.w = fmaf(a2.w, ni9, 0.1f * h2.w);

    if (isFinal) {
        *(float4*)(out + ob + (p    ) * 4) = t0;
        *(float4*)(out + ob + (p + 4) * 4) = t1;
        *(float4*)(out + ob + (p + 8) * 4) = t2;
    } else {
        const float no = g_no[node];
        *(float4*)(nxt + ob + (p    ) * 4) = make_float4(t0.x*no, t0.y*no, t0.z*no, t0.w*no);
        *(float4*)(nxt + ob + (p + 4) * 4) = make_float4(t1.x*no, t1.y*no, t1.z*no, t1.w*no);
        *(float4*)(nxt + ob + (p + 8) * 4) = make_float4(t2.x*no, t2.y*no, t2.z*no, t2.w*no);
    }
}

// ---------------- launch ----------------
extern "C" void kernel_launch(void* const* d_in, const int* in_sizes, int n_in,
                              void* d_out, int out_size)
{
    const float* feats = (const float*)d_in[0];
    const int*   src   = (const int*)d_in[1];
    const int*   dst   = (const int*)d_in[2];
    const float* W1    = (const float*)d_in[3];
    const float* b1    = (const float*)d_in[4];
    const float* W2    = (const float*)d_in[5];
    const float* b2    = (const float*)d_in[6];
    float* out = (float*)d_out;
    (void)in_sizes; (void)n_in; (void)out_size;

    cudaFuncSetAttribute(gemm1_mma_kernel, cudaFuncAttributeMaxDynamicSharedMemorySize, SMEM_G1);

    zero_deg_kernel<<<(2 * NN + 255) / 256, 256>>>();
    count_deg_kernel<<<(EE + 255) / 256, 256>>>(src, dst);
    norm_kernel<<<(NN + 255) / 256, 256>>>();

    scan1_kernel<<<NBLK, SB>>>();
    scan2_kernel<<<1, 1>>>();
    scan3_kernel<<<NBLK, SB>>>();
    fill_kernel<<<(EE + 255) / 256, 256>>>(src, dst);
    binfill_kernel<<<(NN + 255) / 256, 256>>>();

    dim3 grid1((NN + 127) / 128, HIDD / 128);
    gemm1_mma_kernel<<<grid1, 256, SMEM_G1>>>(feats, W1, b1);
    gemm2_kernel<<<(NN + 255) / 256, 256>>>(W2, b2);

    for (int k = 0; k < KIT; k++) {
        prop_kernel<<<(NN * 4 + 255) / 256, 256>>>(k & 1, out, (k == KIT - 1) ? 1 : 0);
    }
}